// round 3
// baseline (speedup 1.0000x reference)
#include <cuda_runtime.h>
#include <cstdint>

#define NLINKS   10000
#define NPATHS   100000
#define PLEN     8
#define HDIM     32
#define RDIM     8
#define TROUNDS  8
#define EDGES    (NPATHS * PLEN)

typedef unsigned long long ULL;

// ---------------- scratch (no cudaMalloc allowed) ----------------
__device__ float g_link_state[NLINKS * HDIM];
__device__ float g_path_state[NPATHS * HDIM];
__device__ float g_hs[(size_t)EDGES * HDIM];   // [s][path][32] layout
__device__ float g_gi[NLINKS * 96];            // per-link input-gate precompute
__device__ int   g_lk[EDGES];                  // link per slot t = 8p+s
__device__ int   g_srow[EDGES];                // sorted pos -> row (s*NPATHS+p)
__device__ int   g_hist[NLINKS];
__device__ int   g_off[NLINKS + 1];
__device__ int   g_cur[NLINKS];

// ---------------- helpers ----------------
__device__ __forceinline__ ULL fma2(ULL a, ULL b, ULL c) {
    ULL d;
    asm("fma.rn.f32x2 %0, %1, %2, %3;" : "=l"(d) : "l"(a), "l"(b), "l"(c));
    return d;
}
__device__ __forceinline__ ULL mul2(ULL a, ULL b) {
    ULL d;
    asm("mul.rn.f32x2 %0, %1, %2;" : "=l"(d) : "l"(a), "l"(b));
    return d;
}
__device__ __forceinline__ ULL pk(float lo, float hi) {
    ULL r;
    asm("mov.b64 %0, {%1, %2};" : "=l"(r) : "f"(lo), "f"(hi));
    return r;
}
__device__ __forceinline__ float hsum2(ULL v) {
    float lo, hi;
    asm("mov.b64 {%0, %1}, %2;" : "=f"(lo), "=f"(hi) : "l"(v));
    return lo + hi;
}
__device__ __forceinline__ float sigmoid_f(float x) {
    return __fdividef(1.f, 1.f + __expf(-x));
}
__device__ __forceinline__ float tanh_f(float x) {
    float e = __expf(2.f * x);
    return 1.f - __fdividef(2.f, e + 1.f);
}

// ---------------- setup A: states, lk map, hist zero -----------------------
__global__ void k_setupA(const float* __restrict__ cap, const float* __restrict__ bw,
                         const int* __restrict__ paths, const int* __restrict__ seqs,
                         const int* __restrict__ links) {
    int i = blockIdx.x * blockDim.x + threadIdx.x;
    if (i < NPATHS * HDIM) g_path_state[i] = ((i & (HDIM - 1)) == 0) ? bw[i / HDIM] : 0.f;
    if (i < NLINKS * HDIM) g_link_state[i] = ((i & (HDIM - 1)) == 0) ? cap[i / HDIM] : 0.f;
    if (i < NLINKS) g_hist[i] = 0;
    if (i < EDGES) g_lk[paths[i] * PLEN + seqs[i]] = links[i];
}

// ---------------- gi matvec (warp per link) --------------------------------
__device__ __forceinline__ void gi_warp(int w, int lane,
                                        const float* sWT, const float* sb) {
    float h = g_link_state[w * HDIM + lane];
    float a0 = sb[lane], a1 = sb[32 + lane], a2 = sb[64 + lane];
#pragma unroll
    for (int k = 0; k < 32; k++) {
        float hv = __shfl_sync(0xffffffffu, h, k);
        a0 += hv * sWT[k * 96 + lane];
        a1 += hv * sWT[k * 96 + 32 + lane];
        a2 += hv * sWT[k * 96 + 64 + lane];
    }
    g_gi[w * 96 + lane] = a0;
    g_gi[w * 96 + 32 + lane] = a1;
    g_gi[w * 96 + 64 + lane] = a2;
}

// ---------------- setup B: histogram + round-0 gi --------------------------
#define HB ((EDGES + 255) / 256)
#define GB ((NLINKS * 32 + 255) / 256)
__global__ __launch_bounds__(256) void k_setupB(
    const int* __restrict__ links,
    const float* __restrict__ pWih, const float* __restrict__ pbih,
    const float* __restrict__ pbhh) {
    if (blockIdx.x < HB) {
        int e = blockIdx.x * 256 + threadIdx.x;
        if (e < EDGES) atomicAdd(&g_hist[links[e]], 1);
        return;
    }
    __shared__ float sWT[HDIM * 96];
    __shared__ float sb[96];
    for (int i = threadIdx.x; i < 96 * HDIM; i += 256) {
        int j = i / HDIM, k = i % HDIM;
        sWT[k * 96 + j] = pWih[i];
    }
    for (int i = threadIdx.x; i < 96; i += 256)
        sb[i] = pbih[i] + (i < 64 ? pbhh[i] : 0.f);
    __syncthreads();
    int w = ((blockIdx.x - HB) * 256 + threadIdx.x) >> 5;
    int lane = threadIdx.x & 31;
    if (w < NLINKS) gi_warp(w, lane, sWT, sb);
}

// ---------------- scan (offsets + cursors) ---------------------------------
__global__ void k_scan() {
    __shared__ int part[1024];
    int tid = threadIdx.x;
    const int CH = (NLINKS + 1023) / 1024;
    int base = tid * CH;
    int s = 0;
    for (int i = 0; i < CH; i++) {
        int idx = base + i;
        if (idx < NLINKS) s += g_hist[idx];
    }
    part[tid] = s;
    __syncthreads();
    for (int off = 1; off < 1024; off <<= 1) {
        int add = (tid >= off) ? part[tid - off] : 0;
        __syncthreads();
        part[tid] += add;
        __syncthreads();
    }
    int run = (tid == 0) ? 0 : part[tid - 1];
    for (int i = 0; i < CH; i++) {
        int idx = base + i;
        if (idx < NLINKS) {
            g_off[idx] = run;
            g_cur[idx] = run;
            run += g_hist[idx];
        }
    }
    if (tid == 1023) g_off[NLINKS] = part[1023];
}

// ---------------- path GRU (dominant kernel) ----------------
// thread-per-path; h @ Whh^T in packed f32x2; gi gathered w/ double-buffer
// prefetch; hop hiddens stored coalesced in [s][path][32] via coop store.
__global__ __launch_bounds__(128, 4) void k_path(
    int build, const float* __restrict__ pWhh, const float* __restrict__ pbhh) {
    __shared__ __align__(16) float sW[96 * HDIM];   // 12.3 KB
    __shared__ float sBn[HDIM];
    __shared__ __align__(16) float sH[128 * 36];    // 18.4 KB

    for (int i = threadIdx.x; i < 96 * HDIM; i += 128) sW[i] = pWhh[i];
    if (threadIdx.x < HDIM) sBn[threadIdx.x] = pbhh[64 + threadIdx.x];
    __syncthreads();

    int p = blockIdx.x * 128 + threadIdx.x;
    if (p >= NPATHS) return;  // whole warps only (99968 = 781 full blocks + 1 warp)
    int lane = threadIdx.x & 31;
    int t0 = threadIdx.x & ~31;
    int pbase = blockIdx.x * 128 + t0;
    float* myH = &sH[threadIdx.x * 36];

    ULL h2[16];
    {
        const ulonglong2* src = (const ulonglong2*)&g_path_state[p * HDIM];
#pragma unroll
        for (int i = 0; i < 8; i++) {
            ulonglong2 v = src[i];
            h2[2 * i] = v.x;
            h2[2 * i + 1] = v.y;
            ((ulonglong2*)myH)[i] = v;
        }
    }

    int lk = g_lk[p * PLEN];
    const float* gi = &g_gi[lk * 96];
    // prefetch first j4 of first step
    float4 gr = __ldg((const float4*)gi);
    float4 gz = __ldg((const float4*)(gi + 32));
    float4 gn = __ldg((const float4*)(gi + 64));

#pragma unroll 1
    for (int s = 0; s < PLEN; s++) {
        int lkn = lk;
        if (s + 1 < PLEN) lkn = g_lk[p * PLEN + s + 1];
        const float* gnext = &g_gi[lkn * 96];

        if (build) {
            int pos = atomicAdd(&g_cur[lk], 1);
            g_srow[pos] = s * NPATHS + p;
        }

#pragma unroll 1
        for (int j4 = 0; j4 < 8; j4++) {
            // prefetch next j4 (or next step's j4=0)
            const float* pf = (j4 < 7) ? (gi + (j4 + 1) * 4) : gnext;
            float4 grn = __ldg((const float4*)pf);
            float4 gzn = __ldg((const float4*)(pf + 32));
            float4 gnn = __ldg((const float4*)(pf + 64));

            float zz[4], nn[4];
#pragma unroll
            for (int u = 0; u < 4; u++) {
                int jj = j4 * 4 + u;
                ULL ar0 = 0, ar1 = 0, az0 = 0, az1 = 0, an0 = 0, an1 = 0;
                const ulonglong2* wr = (const ulonglong2*)&sW[jj * HDIM];
                const ulonglong2* wz = (const ulonglong2*)&sW[(32 + jj) * HDIM];
                const ulonglong2* wn = (const ulonglong2*)&sW[(64 + jj) * HDIM];
#pragma unroll
                for (int q = 0; q < 4; q++) {
                    ulonglong2 w;
                    w = wr[q];     ar0 = fma2(h2[2 * q], w.x, ar0);     ar0 = fma2(h2[2 * q + 1], w.y, ar0);
                    w = wr[q + 4]; ar1 = fma2(h2[2 * q + 8], w.x, ar1); ar1 = fma2(h2[2 * q + 9], w.y, ar1);
                    w = wz[q];     az0 = fma2(h2[2 * q], w.x, az0);     az0 = fma2(h2[2 * q + 1], w.y, az0);
                    w = wz[q + 4]; az1 = fma2(h2[2 * q + 8], w.x, az1); az1 = fma2(h2[2 * q + 9], w.y, az1);
                    w = wn[q];     an0 = fma2(h2[2 * q], w.x, an0);     an0 = fma2(h2[2 * q + 1], w.y, an0);
                    w = wn[q + 4]; an1 = fma2(h2[2 * q + 8], w.x, an1); an1 = fma2(h2[2 * q + 9], w.y, an1);
                }
                float gir = (u == 0) ? gr.x : (u == 1) ? gr.y : (u == 2) ? gr.z : gr.w;
                float giz = (u == 0) ? gz.x : (u == 1) ? gz.y : (u == 2) ? gz.z : gz.w;
                float ginv = (u == 0) ? gn.x : (u == 1) ? gn.y : (u == 2) ? gn.z : gn.w;
                float r = sigmoid_f(gir + hsum2(ar0) + hsum2(ar1));
                float z = sigmoid_f(giz + hsum2(az0) + hsum2(az1));
                float nv = tanh_f(ginv + r * (hsum2(an0) + hsum2(an1) + sBn[jj]));
                zz[u] = z;
                nn[u] = nv;
            }
            // packed blend: h_new = (1-z)*n + z*h_old  (h_old straight from regs)
            ULL hn01 = fma2(pk(zz[0], zz[1]), h2[2 * j4],
                            mul2(pk(1.f - zz[0], 1.f - zz[1]), pk(nn[0], nn[1])));
            ULL hn23 = fma2(pk(zz[2], zz[3]), h2[2 * j4 + 1],
                            mul2(pk(1.f - zz[2], 1.f - zz[3]), pk(nn[2], nn[3])));
            ulonglong2 outv;
            outv.x = hn01;
            outv.y = hn23;
            ((ulonglong2*)myH)[j4] = outv;

            gr = grn; gz = gzn; gn = gnn;
        }
        gi = gnext;
        lk = lkn;

        // refresh packed regs from own smem slice
#pragma unroll
        for (int i = 0; i < 8; i++) {
            ulonglong2 v = ((const ulonglong2*)myH)[i];
            h2[2 * i] = v.x;
            h2[2 * i + 1] = v.y;
        }

        // cooperative coalesced store: one 128B line per iteration
        __syncwarp();
        {
            float* dst = &g_hs[((size_t)s * NPATHS + pbase) * HDIM + lane];
            const float* src = &sH[t0 * 36 + lane];
#pragma unroll 4
            for (int r = 0; r < 32; r++) {
                dst[r * HDIM] = src[r * 36];
            }
        }
        __syncwarp();
    }

    ulonglong2* dst = (ulonglong2*)&g_path_state[p * HDIM];
#pragma unroll
    for (int i = 0; i < 8; i++) {
        ulonglong2 v;
        v.x = h2[2 * i];
        v.y = h2[2 * i + 1];
        dst[i] = v;
    }
}

// ---------------- link aggregation + link GRU (warp per link) ----------------
__global__ __launch_bounds__(256) void k_link(
    const float* __restrict__ lWih, const float* __restrict__ lWhh,
    const float* __restrict__ lbih, const float* __restrict__ lbhh) {
    __shared__ float sWihT[3 * HDIM * HDIM];  // [k][j]
    __shared__ float sWhhT[3 * HDIM * HDIM];
    __shared__ float sbi[3 * HDIM], sbh[3 * HDIM];

    for (int i = threadIdx.x; i < 3 * HDIM * HDIM; i += 256) {
        int j = i / HDIM, k = i % HDIM;
        sWihT[k * 96 + j] = lWih[i];
        sWhhT[k * 96 + j] = lWhh[i];
    }
    for (int i = threadIdx.x; i < 3 * HDIM; i += 256) {
        sbi[i] = lbih[i];
        sbh[i] = lbhh[i];
    }
    __syncthreads();

    int w = (blockIdx.x * 256 + threadIdx.x) >> 5;
    int lane = threadIdx.x & 31;
    if (w >= NLINKS) return;

    int b = g_off[w], e = g_off[w + 1];
    float x0 = 0.f, x1 = 0.f, x2s = 0.f, x3 = 0.f;
    int i = b;
    for (; i + 4 <= e; i += 4) {
        int r0 = g_srow[i], r1 = g_srow[i + 1], r2 = g_srow[i + 2], r3 = g_srow[i + 3];
        x0 += g_hs[(size_t)r0 * HDIM + lane];
        x1 += g_hs[(size_t)r1 * HDIM + lane];
        x2s += g_hs[(size_t)r2 * HDIM + lane];
        x3 += g_hs[(size_t)r3 * HDIM + lane];
    }
    for (; i < e; i++) x0 += g_hs[(size_t)g_srow[i] * HDIM + lane];
    float x = (x0 + x1) + (x2s + x3);

    float h = g_link_state[w * HDIM + lane];

    float air = sbi[lane], aiz = sbi[32 + lane], ain = sbi[64 + lane];
    float ahr = sbh[lane], ahz = sbh[32 + lane], ahn = sbh[64 + lane];
#pragma unroll
    for (int k = 0; k < 32; k++) {
        float xv = __shfl_sync(0xffffffffu, x, k);
        float hv = __shfl_sync(0xffffffffu, h, k);
        air += xv * sWihT[k * 96 + lane];
        aiz += xv * sWihT[k * 96 + 32 + lane];
        ain += xv * sWihT[k * 96 + 64 + lane];
        ahr += hv * sWhhT[k * 96 + lane];
        ahz += hv * sWhhT[k * 96 + 32 + lane];
        ahn += hv * sWhhT[k * 96 + 64 + lane];
    }
    float r = sigmoid_f(air + ahr);
    float z = sigmoid_f(aiz + ahz);
    float nv = tanh_f(ain + r * ahn);
    g_link_state[w * HDIM + lane] = (1.f - z) * nv + z * h;
}

// ---------------- per-round gi (rounds >= 1) --------------------------------
__global__ __launch_bounds__(256) void k_gi(
    const float* __restrict__ pWih, const float* __restrict__ pbih,
    const float* __restrict__ pbhh) {
    __shared__ float sWT[HDIM * 96];
    __shared__ float sb[96];
    for (int i = threadIdx.x; i < 96 * HDIM; i += 256) {
        int j = i / HDIM, k = i % HDIM;
        sWT[k * 96 + j] = pWih[i];
    }
    for (int i = threadIdx.x; i < 96; i += 256)
        sb[i] = pbih[i] + (i < 64 ? pbhh[i] : 0.f);
    __syncthreads();
    int w = (blockIdx.x * 256 + threadIdx.x) >> 5;
    int lane = threadIdx.x & 31;
    if (w < NLINKS) gi_warp(w, lane, sWT, sb);
}

// ---------------- readout MLP ----------------
__global__ __launch_bounds__(256) void k_readout(
    const float* __restrict__ W1, const float* __restrict__ b1,
    const float* __restrict__ W2, const float* __restrict__ b2,
    const float* __restrict__ W3, const float* __restrict__ b3,
    float* __restrict__ out) {
    __shared__ float s1[RDIM * HDIM], sb1[RDIM], s2[RDIM * RDIM], sb2[RDIM], s3[RDIM], sb3;
    for (int i = threadIdx.x; i < RDIM * HDIM; i += 256) s1[i] = W1[i];
    if (threadIdx.x < RDIM * RDIM) s2[threadIdx.x] = W2[threadIdx.x];
    if (threadIdx.x < RDIM) {
        sb1[threadIdx.x] = b1[threadIdx.x];
        sb2[threadIdx.x] = b2[threadIdx.x];
        s3[threadIdx.x] = W3[threadIdx.x];
    }
    if (threadIdx.x == 0) sb3 = b3[0];
    __syncthreads();

    int p = blockIdx.x * 256 + threadIdx.x;
    if (p >= NPATHS) return;

    float x[HDIM];
    {
        const float4* src = (const float4*)&g_path_state[p * HDIM];
#pragma unroll
        for (int i = 0; i < 8; i++) {
            float4 v = src[i];
            x[4 * i] = v.x; x[4 * i + 1] = v.y; x[4 * i + 2] = v.z; x[4 * i + 3] = v.w;
        }
    }
    float y1[RDIM];
#pragma unroll
    for (int i = 0; i < RDIM; i++) {
        float d = sb1[i];
#pragma unroll
        for (int k = 0; k < HDIM; k++) d += x[k] * s1[i * HDIM + k];
        y1[i] = fmaxf(d, 0.f);
    }
    float y2[RDIM];
#pragma unroll
    for (int i = 0; i < RDIM; i++) {
        float d = sb2[i];
#pragma unroll
        for (int k = 0; k < RDIM; k++) d += y1[k] * s2[i * RDIM + k];
        y2[i] = fmaxf(d, 0.f);
    }
    float o = sb3;
#pragma unroll
    for (int k = 0; k < RDIM; k++) o += y2[k] * s3[k];
    out[p] = o;
}

// ---------------- launch ----------------
extern "C" void kernel_launch(void* const* d_in, const int* in_sizes, int n_in,
                              void* d_out, int out_size) {
    const int* links = (const int*)d_in[0];
    const int* paths = (const int*)d_in[1];
    const int* seqs  = (const int*)d_in[2];
    const float* cap = (const float*)d_in[3];
    const float* bw  = (const float*)d_in[4];
    const float* pWih = (const float*)d_in[5];
    const float* pWhh = (const float*)d_in[6];
    const float* pbih = (const float*)d_in[7];
    const float* pbhh = (const float*)d_in[8];
    const float* lWih = (const float*)d_in[9];
    const float* lWhh = (const float*)d_in[10];
    const float* lbih = (const float*)d_in[11];
    const float* lbhh = (const float*)d_in[12];
    const float* W1 = (const float*)d_in[13];
    const float* b1 = (const float*)d_in[14];
    const float* W2 = (const float*)d_in[15];
    const float* b2 = (const float*)d_in[16];
    const float* W3 = (const float*)d_in[17];
    const float* b3 = (const float*)d_in[18];
    float* out = (float*)d_out;

    (void)in_sizes; (void)n_in; (void)out_size;

    k_setupA<<<(NPATHS * HDIM + 255) / 256, 256>>>(cap, bw, paths, seqs, links);
    k_setupB<<<HB + GB, 256>>>(links, pWih, pbih, pbhh);
    k_scan<<<1, 1024>>>();

    for (int r = 0; r < TROUNDS; r++) {
        k_path<<<(NPATHS + 127) / 128, 128>>>(r == 0 ? 1 : 0, pWhh, pbhh);
        k_link<<<(NLINKS + 7) / 8, 256>>>(lWih, lWhh, lbih, lbhh);
        if (r + 1 < TROUNDS)
            k_gi<<<(NLINKS * 32 + 255) / 256, 256>>>(pWih, pbih, pbhh);
    }
    k_readout<<<(NPATHS + 255) / 256, 256>>>(W1, b1, W2, b2, W3, b3, out);
}

// round 4
// speedup vs baseline: 1.2134x; 1.2134x over previous
#include <cuda_runtime.h>
#include <cstdint>

#define NLINKS   10000
#define NPATHS   100000
#define PLEN     8
#define HDIM     32
#define RDIM     8
#define TROUNDS  8
#define EDGES    (NPATHS * PLEN)

typedef unsigned long long ULL;

// ---------------- scratch (no cudaMalloc allowed) ----------------
__device__ float g_link_state[NLINKS * HDIM];
__device__ float g_path_state[NPATHS * HDIM];
__device__ float g_hs[(size_t)EDGES * HDIM];   // [s][path][32] layout
__device__ float g_gi[NLINKS * 96];            // per-link input-gate precompute
__device__ int   g_lk[EDGES];                  // link per slot t = 8p+s
__device__ int   g_srow[EDGES];                // sorted pos -> row (s*NPATHS+p)
__device__ int   g_hist[NLINKS];
__device__ int   g_off[NLINKS + 1];
__device__ int   g_cur[NLINKS];

// ---------------- helpers ----------------
__device__ __forceinline__ ULL fma2(ULL a, ULL b, ULL c) {
    ULL d;
    asm("fma.rn.f32x2 %0, %1, %2, %3;" : "=l"(d) : "l"(a), "l"(b), "l"(c));
    return d;
}
__device__ __forceinline__ ULL mul2(ULL a, ULL b) {
    ULL d;
    asm("mul.rn.f32x2 %0, %1, %2;" : "=l"(d) : "l"(a), "l"(b));
    return d;
}
__device__ __forceinline__ ULL pk(float lo, float hi) {
    ULL r;
    asm("mov.b64 %0, {%1, %2};" : "=l"(r) : "f"(lo), "f"(hi));
    return r;
}
__device__ __forceinline__ float hsum2(ULL v) {
    float lo, hi;
    asm("mov.b64 {%0, %1}, %2;" : "=f"(lo), "=f"(hi) : "l"(v));
    return lo + hi;
}
__device__ __forceinline__ float tanh_fast(float x) {
    float y;
    asm("tanh.approx.f32 %0, %1;" : "=f"(y) : "f"(x));
    return y;
}
__device__ __forceinline__ float sigmoid_fast(float x) {
    return fmaf(0.5f, tanh_fast(0.5f * x), 0.5f);
}

// ---------------- setup A: states, lk map, hist zero -----------------------
__global__ void k_setupA(const float* __restrict__ cap, const float* __restrict__ bw,
                         const int* __restrict__ paths, const int* __restrict__ seqs,
                         const int* __restrict__ links) {
    int i = blockIdx.x * blockDim.x + threadIdx.x;
    if (i < NPATHS * HDIM) g_path_state[i] = ((i & (HDIM - 1)) == 0) ? bw[i / HDIM] : 0.f;
    if (i < NLINKS * HDIM) g_link_state[i] = ((i & (HDIM - 1)) == 0) ? cap[i / HDIM] : 0.f;
    if (i < NLINKS) g_hist[i] = 0;
    if (i < EDGES) g_lk[paths[i] * PLEN + seqs[i]] = links[i];
}

// ---------------- gi matvec from link_state (round-0 only) -----------------
__device__ __forceinline__ void gi_warp(int w, int lane,
                                        const float* sWT, const float* sb) {
    float h = g_link_state[w * HDIM + lane];
    float a0 = sb[lane], a1 = sb[32 + lane], a2 = sb[64 + lane];
#pragma unroll
    for (int k = 0; k < 32; k++) {
        float hv = __shfl_sync(0xffffffffu, h, k);
        a0 += hv * sWT[k * 96 + lane];
        a1 += hv * sWT[k * 96 + 32 + lane];
        a2 += hv * sWT[k * 96 + 64 + lane];
    }
    g_gi[w * 96 + lane] = a0;
    g_gi[w * 96 + 32 + lane] = a1;
    g_gi[w * 96 + 64 + lane] = a2;
}

// ---------------- setup B: histogram + round-0 gi --------------------------
#define HB ((EDGES + 255) / 256)
#define GB ((NLINKS * 32 + 255) / 256)
__global__ __launch_bounds__(256) void k_setupB(
    const int* __restrict__ links,
    const float* __restrict__ pWih, const float* __restrict__ pbih,
    const float* __restrict__ pbhh) {
    if (blockIdx.x < HB) {
        int e = blockIdx.x * 256 + threadIdx.x;
        if (e < EDGES) atomicAdd(&g_hist[links[e]], 1);
        return;
    }
    __shared__ float sWT[HDIM * 96];
    __shared__ float sb[96];
    for (int i = threadIdx.x; i < 96 * HDIM; i += 256) {
        int j = i / HDIM, k = i % HDIM;
        sWT[k * 96 + j] = pWih[i];
    }
    for (int i = threadIdx.x; i < 96; i += 256)
        sb[i] = pbih[i] + (i < 64 ? pbhh[i] : 0.f);
    __syncthreads();
    int w = ((blockIdx.x - HB) * 256 + threadIdx.x) >> 5;
    int lane = threadIdx.x & 31;
    if (w < NLINKS) gi_warp(w, lane, sWT, sb);
}

// ---------------- scan (offsets + cursors) ---------------------------------
__global__ void k_scan() {
    __shared__ int part[1024];
    int tid = threadIdx.x;
    const int CH = (NLINKS + 1023) / 1024;
    int base = tid * CH;
    int s = 0;
    for (int i = 0; i < CH; i++) {
        int idx = base + i;
        if (idx < NLINKS) s += g_hist[idx];
    }
    part[tid] = s;
    __syncthreads();
    for (int off = 1; off < 1024; off <<= 1) {
        int add = (tid >= off) ? part[tid - off] : 0;
        __syncthreads();
        part[tid] += add;
        __syncthreads();
    }
    int run = (tid == 0) ? 0 : part[tid - 1];
    for (int i = 0; i < CH; i++) {
        int idx = base + i;
        if (idx < NLINKS) {
            g_off[idx] = run;
            g_cur[idx] = run;
            run += g_hist[idx];
        }
    }
    if (tid == 1023) g_off[NLINKS] = part[1023];
}

// ---------------- path GRU (dominant kernel) ----------------
// 64-thread CTA (2 warps, warp-independent). Per step:
//  - gi rows staged coalesced via cp.async into per-thread stride-100 slices
//  - h @ Whh^T in packed f32x2, weights broadcast LDS.128
//  - gates via tanh.approx; blend; coalesced coop store of hop hiddens
__global__ __launch_bounds__(64) void k_path(
    int build, const float* __restrict__ pWhh, const float* __restrict__ pbhh) {
    __shared__ __align__(16) float sW[96 * HDIM];   // 12.3 KB
    __shared__ __align__(16) float sBn[HDIM];
    __shared__ __align__(16) float sGi[64 * 100];   // 25.6 KB
    __shared__ __align__(16) float sH[64 * 36];     // 9.2 KB
    __shared__ int sLk[64];

    for (int i = threadIdx.x; i < 96 * HDIM; i += 64) sW[i] = pWhh[i];
    if (threadIdx.x < HDIM) sBn[threadIdx.x] = pbhh[64 + threadIdx.x];
    __syncthreads();

    int tid = threadIdx.x;
    int p = blockIdx.x * 64 + tid;
    if (p >= NPATHS) return;  // NPATHS % 32 == 0: whole warps only
    int lane = tid & 31, t0 = tid & ~31;
    int pbase = blockIdx.x * 64 + t0;
    float* myH = &sH[tid * 36];
    float* myGi = &sGi[tid * 100];
    unsigned sgi_warp = (unsigned)__cvta_generic_to_shared(&sGi[t0 * 100]);

    ULL h2[16];
    {
        const ulonglong2* src = (const ulonglong2*)&g_path_state[p * HDIM];
#pragma unroll
        for (int i = 0; i < 8; i++) {
            ulonglong2 v = src[i];
            h2[2 * i] = v.x;
            h2[2 * i + 1] = v.y;
            ((ulonglong2*)myH)[i] = v;
        }
    }

#pragma unroll 1
    for (int s = 0; s < PLEN; s++) {
        int lk = g_lk[p * PLEN + s];
        sLk[tid] = lk;
        __syncwarp();
        // ---- stage this warp's 32 gi rows, coalesced (24 x 16B per thread id)
#pragma unroll
        for (int it = 0; it < 24; it++) {
            int idx = it * 32 + lane;
            int m = idx / 24;
            int c = idx - m * 24;
            int lkv = sLk[t0 + m];
            const float* srcp = &g_gi[lkv * 96 + c * 4];
            unsigned dst = sgi_warp + (unsigned)(m * 400 + c * 16);
            asm volatile("cp.async.cg.shared.global [%0], [%1], 16;" :: "r"(dst), "l"(srcp));
        }
        asm volatile("cp.async.commit_group;");
        if (build) {
            int pos = atomicAdd(&g_cur[lk], 1);
            g_srow[pos] = s * NPATHS + p;
        }
        asm volatile("cp.async.wait_group 0;" ::: "memory");
        __syncwarp();

#pragma unroll 1
        for (int j4 = 0; j4 < 8; j4++) {
            float4 gr = *(const float4*)(myGi + j4 * 4);
            float4 gz = *(const float4*)(myGi + 32 + j4 * 4);
            float4 gn = *(const float4*)(myGi + 64 + j4 * 4);
            float4 bn4 = *(const float4*)(sBn + j4 * 4);
            ulonglong2 hb = ((const ulonglong2*)myH)[j4];

            float zz[4], nn[4];
#pragma unroll
            for (int u = 0; u < 4; u++) {
                int jj = j4 * 4 + u;
                ULL ar0 = 0, ar1 = 0, az0 = 0, az1 = 0, an0 = 0, an1 = 0;
                const ulonglong2* wr = (const ulonglong2*)&sW[jj * HDIM];
                const ulonglong2* wz = (const ulonglong2*)&sW[(32 + jj) * HDIM];
                const ulonglong2* wn = (const ulonglong2*)&sW[(64 + jj) * HDIM];
#pragma unroll
                for (int q = 0; q < 4; q++) {
                    ulonglong2 w;
                    w = wr[q];     ar0 = fma2(h2[2 * q], w.x, ar0);     ar0 = fma2(h2[2 * q + 1], w.y, ar0);
                    w = wr[q + 4]; ar1 = fma2(h2[2 * q + 8], w.x, ar1); ar1 = fma2(h2[2 * q + 9], w.y, ar1);
                    w = wz[q];     az0 = fma2(h2[2 * q], w.x, az0);     az0 = fma2(h2[2 * q + 1], w.y, az0);
                    w = wz[q + 4]; az1 = fma2(h2[2 * q + 8], w.x, az1); az1 = fma2(h2[2 * q + 9], w.y, az1);
                    w = wn[q];     an0 = fma2(h2[2 * q], w.x, an0);     an0 = fma2(h2[2 * q + 1], w.y, an0);
                    w = wn[q + 4]; an1 = fma2(h2[2 * q + 8], w.x, an1); an1 = fma2(h2[2 * q + 9], w.y, an1);
                }
                float gir = (u == 0) ? gr.x : (u == 1) ? gr.y : (u == 2) ? gr.z : gr.w;
                float giz = (u == 0) ? gz.x : (u == 1) ? gz.y : (u == 2) ? gz.z : gz.w;
                float ginv = (u == 0) ? gn.x : (u == 1) ? gn.y : (u == 2) ? gn.z : gn.w;
                float bnv = (u == 0) ? bn4.x : (u == 1) ? bn4.y : (u == 2) ? bn4.z : bn4.w;
                float r = sigmoid_fast(gir + hsum2(ar0) + hsum2(ar1));
                float z = sigmoid_fast(giz + hsum2(az0) + hsum2(az1));
                float nv = tanh_fast(ginv + r * (hsum2(an0) + hsum2(an1) + bnv));
                zz[u] = z;
                nn[u] = nv;
            }
            // packed blend: h_new = (1-z)*n + z*h_old; myH[j4] free to overwrite
            ULL hn01 = fma2(pk(zz[0], zz[1]), hb.x,
                            mul2(pk(1.f - zz[0], 1.f - zz[1]), pk(nn[0], nn[1])));
            ULL hn23 = fma2(pk(zz[2], zz[3]), hb.y,
                            mul2(pk(1.f - zz[2], 1.f - zz[3]), pk(nn[2], nn[3])));
            ulonglong2 outv;
            outv.x = hn01;
            outv.y = hn23;
            ((ulonglong2*)myH)[j4] = outv;
        }

        __syncwarp();
        // refresh packed regs from own slice
#pragma unroll
        for (int i = 0; i < 8; i++) {
            ulonglong2 v = ((const ulonglong2*)myH)[i];
            h2[2 * i] = v.x;
            h2[2 * i + 1] = v.y;
        }
        // cooperative coalesced store of this warp's 32 hop-hidden rows
        {
            float* dst = &g_hs[((size_t)s * NPATHS + pbase) * HDIM + lane];
            const float* srcp = &sH[t0 * 36 + lane];
#pragma unroll 4
            for (int r = 0; r < 32; r++) {
                dst[r * HDIM] = srcp[r * 36];
            }
        }
        __syncwarp();
    }

    ulonglong2* dst = (ulonglong2*)&g_path_state[p * HDIM];
#pragma unroll
    for (int i = 0; i < 8; i++) {
        ulonglong2 v;
        v.x = h2[2 * i];
        v.y = h2[2 * i + 1];
        dst[i] = v;
    }
}

// ---------- link aggregation + link GRU + fused next-round gi --------------
__global__ __launch_bounds__(256) void k_link(
    int dogi,
    const float* __restrict__ lWih, const float* __restrict__ lWhh,
    const float* __restrict__ lbih, const float* __restrict__ lbhh,
    const float* __restrict__ pWih, const float* __restrict__ pbih,
    const float* __restrict__ pbhh) {
    __shared__ float sWihT[3 * HDIM * HDIM];  // [k][j]
    __shared__ float sWhhT[3 * HDIM * HDIM];
    __shared__ float sPT[3 * HDIM * HDIM];    // path Wih^T for gi
    __shared__ float sbi[96], sbh[96], sgb[96];

    for (int i = threadIdx.x; i < 3 * HDIM * HDIM; i += 256) {
        int j = i / HDIM, k = i % HDIM;
        sWihT[k * 96 + j] = lWih[i];
        sWhhT[k * 96 + j] = lWhh[i];
        sPT[k * 96 + j] = pWih[i];
    }
    for (int i = threadIdx.x; i < 96; i += 256) {
        sbi[i] = lbih[i];
        sbh[i] = lbhh[i];
        sgb[i] = pbih[i] + (i < 64 ? pbhh[i] : 0.f);
    }
    __syncthreads();

    int w = (blockIdx.x * 256 + threadIdx.x) >> 5;
    int lane = threadIdx.x & 31;
    if (w >= NLINKS) return;

    int b = g_off[w], e = g_off[w + 1];
    float x0 = 0.f, x1 = 0.f, x2s = 0.f, x3 = 0.f;
    int i = b;
    for (; i + 4 <= e; i += 4) {
        int r0 = g_srow[i], r1 = g_srow[i + 1], r2 = g_srow[i + 2], r3 = g_srow[i + 3];
        x0 += g_hs[(size_t)r0 * HDIM + lane];
        x1 += g_hs[(size_t)r1 * HDIM + lane];
        x2s += g_hs[(size_t)r2 * HDIM + lane];
        x3 += g_hs[(size_t)r3 * HDIM + lane];
    }
    for (; i < e; i++) x0 += g_hs[(size_t)g_srow[i] * HDIM + lane];
    float x = (x0 + x1) + (x2s + x3);

    float h = g_link_state[w * HDIM + lane];

    float air = sbi[lane], aiz = sbi[32 + lane], ain = sbi[64 + lane];
    float ahr = sbh[lane], ahz = sbh[32 + lane], ahn = sbh[64 + lane];
#pragma unroll
    for (int k = 0; k < 32; k++) {
        float xv = __shfl_sync(0xffffffffu, x, k);
        float hv = __shfl_sync(0xffffffffu, h, k);
        air += xv * sWihT[k * 96 + lane];
        aiz += xv * sWihT[k * 96 + 32 + lane];
        ain += xv * sWihT[k * 96 + 64 + lane];
        ahr += hv * sWhhT[k * 96 + lane];
        ahz += hv * sWhhT[k * 96 + 32 + lane];
        ahn += hv * sWhhT[k * 96 + 64 + lane];
    }
    float r = sigmoid_fast(air + ahr);
    float z = sigmoid_fast(aiz + ahz);
    float nv = tanh_fast(ain + r * ahn);
    float hnew = (1.f - z) * nv + z * h;
    g_link_state[w * HDIM + lane] = hnew;

    if (dogi) {
        float a0 = sgb[lane], a1 = sgb[32 + lane], a2 = sgb[64 + lane];
#pragma unroll
        for (int k = 0; k < 32; k++) {
            float hv = __shfl_sync(0xffffffffu, hnew, k);
            a0 += hv * sPT[k * 96 + lane];
            a1 += hv * sPT[k * 96 + 32 + lane];
            a2 += hv * sPT[k * 96 + 64 + lane];
        }
        g_gi[w * 96 + lane] = a0;
        g_gi[w * 96 + 32 + lane] = a1;
        g_gi[w * 96 + 64 + lane] = a2;
    }
}

// ---------------- readout MLP ----------------
__global__ __launch_bounds__(256) void k_readout(
    const float* __restrict__ W1, const float* __restrict__ b1,
    const float* __restrict__ W2, const float* __restrict__ b2,
    const float* __restrict__ W3, const float* __restrict__ b3,
    float* __restrict__ out) {
    __shared__ float s1[RDIM * HDIM], sb1[RDIM], s2[RDIM * RDIM], sb2[RDIM], s3[RDIM], sb3;
    for (int i = threadIdx.x; i < RDIM * HDIM; i += 256) s1[i] = W1[i];
    if (threadIdx.x < RDIM * RDIM) s2[threadIdx.x] = W2[threadIdx.x];
    if (threadIdx.x < RDIM) {
        sb1[threadIdx.x] = b1[threadIdx.x];
        sb2[threadIdx.x] = b2[threadIdx.x];
        s3[threadIdx.x] = W3[threadIdx.x];
    }
    if (threadIdx.x == 0) sb3 = b3[0];
    __syncthreads();

    int p = blockIdx.x * 256 + threadIdx.x;
    if (p >= NPATHS) return;

    float x[HDIM];
    {
        const float4* src = (const float4*)&g_path_state[p * HDIM];
#pragma unroll
        for (int i = 0; i < 8; i++) {
            float4 v = src[i];
            x[4 * i] = v.x; x[4 * i + 1] = v.y; x[4 * i + 2] = v.z; x[4 * i + 3] = v.w;
        }
    }
    float y1[RDIM];
#pragma unroll
    for (int i = 0; i < RDIM; i++) {
        float d = sb1[i];
#pragma unroll
        for (int k = 0; k < HDIM; k++) d += x[k] * s1[i * HDIM + k];
        y1[i] = fmaxf(d, 0.f);
    }
    float y2[RDIM];
#pragma unroll
    for (int i = 0; i < RDIM; i++) {
        float d = sb2[i];
#pragma unroll
        for (int k = 0; k < RDIM; k++) d += y1[k] * s2[i * RDIM + k];
        y2[i] = fmaxf(d, 0.f);
    }
    float o = sb3;
#pragma unroll
    for (int k = 0; k < RDIM; k++) o += y2[k] * s3[k];
    out[p] = o;
}

// ---------------- launch ----------------
extern "C" void kernel_launch(void* const* d_in, const int* in_sizes, int n_in,
                              void* d_out, int out_size) {
    const int* links = (const int*)d_in[0];
    const int* paths = (const int*)d_in[1];
    const int* seqs  = (const int*)d_in[2];
    const float* cap = (const float*)d_in[3];
    const float* bw  = (const float*)d_in[4];
    const float* pWih = (const float*)d_in[5];
    const float* pWhh = (const float*)d_in[6];
    const float* pbih = (const float*)d_in[7];
    const float* pbhh = (const float*)d_in[8];
    const float* lWih = (const float*)d_in[9];
    const float* lWhh = (const float*)d_in[10];
    const float* lbih = (const float*)d_in[11];
    const float* lbhh = (const float*)d_in[12];
    const float* W1 = (const float*)d_in[13];
    const float* b1 = (const float*)d_in[14];
    const float* W2 = (const float*)d_in[15];
    const float* b2 = (const float*)d_in[16];
    const float* W3 = (const float*)d_in[17];
    const float* b3 = (const float*)d_in[18];
    float* out = (float*)d_out;

    (void)in_sizes; (void)n_in; (void)out_size;

    k_setupA<<<(NPATHS * HDIM + 255) / 256, 256>>>(cap, bw, paths, seqs, links);
    k_setupB<<<HB + GB, 256>>>(links, pWih, pbih, pbhh);
    k_scan<<<1, 1024>>>();

    for (int r = 0; r < TROUNDS; r++) {
        k_path<<<(NPATHS + 63) / 64, 64>>>(r == 0 ? 1 : 0, pWhh, pbhh);
        k_link<<<(NLINKS + 7) / 8, 256>>>(r + 1 < TROUNDS ? 1 : 0,
                                          lWih, lWhh, lbih, lbhh,
                                          pWih, pbih, pbhh);
    }
    k_readout<<<(NPATHS + 255) / 256, 256>>>(W1, b1, W2, b2, W3, b3, out);
}